// round 17
// baseline (speedup 1.0000x reference)
#include <cuda_runtime.h>
#include <cuda_bf16.h>
#include <cstdint>

// Problem constants (shapes fixed by the dataset)
#define DD 128
#define NN 50000
#define EE 600000

// Scratch (no runtime allocation allowed).
// NOTE: only touch from device code or via cudaGetSymbolAddress — passing the
// symbol itself from host passes the HOST shadow address, which GB300 ATS
// serves over NVLink-C2C at 200 GB/s (the 3.6 ms R10/R11 bug).
__device__ __align__(16) float g_tmp1[NN * DD];
__device__ __align__(16) float g_tmp2[NN * DD];
__device__ float g_degf[NN];
__device__ int   g_cnt[NN];
__device__ int   g_cursor[NN];
__device__ int   g_off[NN + 1];
__device__ __align__(8) int2 g_srcw[EE];  // CSR slots: {src row, norm bits}

// ---------------------------------------------------------------------------
__global__ void zero_kernel(int n) {
    int i = blockIdx.x * blockDim.x + threadIdx.x;
    if (i < n) { g_cnt[i] = 0; g_cursor[i] = 0; g_degf[i] = 0.f; }
}

// Per-destination: edge count (int atomic) + weighted degree (float atomic).
__global__ void count_kernel(const int* __restrict__ adj,
                             const float* __restrict__ ew, int E, int N) {
    int e = blockIdx.x * blockDim.x + threadIdx.x;
    if (e < E) {
        int col = adj[E + e];
        if ((unsigned)col < (unsigned)N) {
            atomicAdd(&g_cnt[col], 1);
            atomicAdd(&g_degf[col], ew[e]);
        }
    }
}

// Exclusive scan of cnt into off, single 1024-thread block.
__global__ __launch_bounds__(1024) void scan_kernel(int N) {
    __shared__ int s[1024];
    const int t = threadIdx.x;
    const int CH = (NN + 1023) / 1024;            // 49
    int base = t * CH;
    int sum = 0;
    for (int i = 0; i < CH; i++) {
        int idx = base + i;
        if (idx < N) sum += g_cnt[idx];
    }
    s[t] = sum;
    __syncthreads();
    for (int d = 1; d < 1024; d <<= 1) {
        int v = (t >= d) ? s[t - d] : 0;
        __syncthreads();
        s[t] += v;
        __syncthreads();
    }
    int start = (t == 0) ? 0 : s[t - 1];
    for (int i = 0; i < CH; i++) {
        int idx = base + i;
        if (idx < N) { g_off[idx] = start; start += g_cnt[idx]; }
    }
    if (t == 1023) g_off[N] = s[1023];
}

// Fill CSR slots directly with {src row, normalized weight}.
__global__ void fill_kernel(const int* __restrict__ adj,
                            const float* __restrict__ ew, int E, int N) {
    int e = blockIdx.x * blockDim.x + threadIdx.x;
    if (e >= E) return;
    int col = adj[E + e];
    if ((unsigned)col >= (unsigned)N) return;
    int row = adj[e];
    float degr = ((unsigned)row < (unsigned)N) ? g_degf[row] : 0.f;
    float degc = g_degf[col];
    float dr = (degr > 0.f) ? rsqrtf(degr) : 0.f;
    float dc = (degc > 0.f) ? rsqrtf(degc) : 0.f;
    float w = dr * ew[e] * dc;
    int r = ((unsigned)row < (unsigned)N) ? row : 0;   // w==0 if clamped
    int pos = atomicAdd(&g_cursor[col], 1);
    g_srcw[g_off[col] + pos] = make_int2(r, __float_as_int(w));
}

// ---------------------------------------------------------------------------
// GEMM: C[M,128] = A[M,128] @ W[128,128], fp32.
// 128x128 block tile, 256 threads, 8x8 register tile -> 64 FFMA per
// 10-instruction inner step (~86% FMA density vs 78% for the 8x4 version).
// __launch_bounds__(256,2): <=128 regs, 2 CTAs/SM (full RF).
// ---------------------------------------------------------------------------
__global__ __launch_bounds__(256, 2) void gemm_kernel(
    const float* __restrict__ A, const float* __restrict__ W,
    float* __restrict__ C, int M) {
    __shared__ float xs[128][32];   // A tile: rows x k-chunk
    __shared__ float ws[32][128];   // W tile: k-chunk x cols

    const int t  = threadIdx.x;
    const int tx = t & 15;          // col group: cols [tx*8, tx*8+7]
    const int ty = t >> 4;          // row group: rows [ty*8, ty*8+7]
    const int rowBase = blockIdx.x * 128;

    float acc[8][8];
#pragma unroll
    for (int r = 0; r < 8; r++)
#pragma unroll
        for (int c = 0; c < 8; c++) acc[r][c] = 0.f;

    for (int kc = 0; kc < 4; kc++) {
        // Load A tile: 128x32 floats = 1024 float4, 4 per thread, coalesced.
#pragma unroll
        for (int i = 0; i < 4; i++) {
            int linear = i * 256 + t;
            int row = linear >> 3, f4 = linear & 7;
            int grow = rowBase + row;
            float4 v = (grow < M)
                ? *(const float4*)&A[(size_t)grow * DD + kc * 32 + f4 * 4]
                : make_float4(0.f, 0.f, 0.f, 0.f);
            *(float4*)&xs[row][f4 * 4] = v;
        }
        // Load W tile: 32x128 floats = 1024 float4, 4 per thread, coalesced.
#pragma unroll
        for (int i = 0; i < 4; i++) {
            int linear = i * 256 + t;
            int k = linear >> 5, f4 = linear & 31;
            *(float4*)&ws[k][f4 * 4] =
                *(const float4*)&W[(size_t)(kc * 32 + k) * DD + f4 * 4];
        }
        __syncthreads();

#pragma unroll 4
        for (int k = 0; k < 32; k++) {
            float4 b0 = *(const float4*)&ws[k][tx * 8];
            float4 b1 = *(const float4*)&ws[k][tx * 8 + 4];
            float a[8];
#pragma unroll
            for (int r = 0; r < 8; r++) a[r] = xs[ty * 8 + r][k];
#pragma unroll
            for (int r = 0; r < 8; r++) {
                acc[r][0] += a[r] * b0.x;
                acc[r][1] += a[r] * b0.y;
                acc[r][2] += a[r] * b0.z;
                acc[r][3] += a[r] * b0.w;
                acc[r][4] += a[r] * b1.x;
                acc[r][5] += a[r] * b1.y;
                acc[r][6] += a[r] * b1.z;
                acc[r][7] += a[r] * b1.w;
            }
        }
        __syncthreads();
    }

#pragma unroll
    for (int r = 0; r < 8; r++) {
        int grow = rowBase + ty * 8 + r;
        if (grow < M) {
            *(float4*)&C[(size_t)grow * DD + tx * 8] =
                make_float4(acc[r][0], acc[r][1], acc[r][2], acc[r][3]);
            *(float4*)&C[(size_t)grow * DD + tx * 8 + 4] =
                make_float4(acc[r][4], acc[r][5], acc[r][6], acc[r][7]);
        }
    }
}

// ---------------------------------------------------------------------------
// Warp-cooperative CSR gather + fused epilogue. One warp per destination
// node; lane owns 4 features. One coalesced int2 metadata load covers 32
// edges; rows broadcast via shfl while independent 512B row-gathers issue.
// ---------------------------------------------------------------------------
template <bool RESID>
__global__ __launch_bounds__(256) void gather_kernel(
    const float* __restrict__ src, const float* __restrict__ bias,
    const float* __restrict__ resid,
    float* __restrict__ dst, int N) {
    int g = blockIdx.x * blockDim.x + threadIdx.x;
    int n = g >> 5, lane = g & 31;
    if (n >= N) return;

    const int j0 = g_off[n], j1 = g_off[n + 1];
    const int fo = lane << 2;
    float ax = 0.f, ay = 0.f, az = 0.f, aw = 0.f;

    for (int base = j0; base < j1; base += 32) {
        int jj = base + lane;
        int2 sw = (jj < j1) ? g_srcw[jj] : make_int2(0, 0);
        int cnt = min(32, j1 - base);
#pragma unroll 4
        for (int i = 0; i < cnt; i++) {
            int   r = __shfl_sync(0xFFFFFFFFu, sw.x, i);
            float w = __int_as_float(__shfl_sync(0xFFFFFFFFu, sw.y, i));
            float4 v = *(const float4*)(src + (size_t)r * DD + fo);
            ax += w * v.x; ay += w * v.y; az += w * v.z; aw += w * v.w;
        }
    }

    float4 b = *(const float4*)(bias + fo);
    ax = fmaxf(ax + b.x, 0.f);
    ay = fmaxf(ay + b.y, 0.f);
    az = fmaxf(az + b.z, 0.f);
    aw = fmaxf(aw + b.w, 0.f);
    if (RESID) {
        float4 rv = *(const float4*)(resid + (size_t)n * DD + fo);
        ax += rv.x; ay += rv.y; az += rv.z; aw += rv.w;
    }
    *(float4*)(dst + (size_t)n * DD + fo) = make_float4(ax, ay, az, aw);
}

// ---------------------------------------------------------------------------
extern "C" void kernel_launch(void* const* d_in, const int* in_sizes, int n_in,
                              void* d_out, int out_size) {
    const float* x   = (const float*)d_in[0];
    const int*   adj = (const int*)d_in[1];     // int32 [2, E]
    const float* ew  = (const float*)d_in[2];
    const float* W1  = (const float*)d_in[3];
    const float* b1  = (const float*)d_in[4];
    const float* W2  = (const float*)d_in[5];
    const float* b2  = (const float*)d_in[6];
    float*       out = (float*)d_out;

    const int E = in_sizes[2];           // 600000
    const int N = in_sizes[0] / DD;      // 50000

    // REAL device addresses (see note at the symbol definitions).
    float* tmp1 = nullptr;
    float* tmp2 = nullptr;
    cudaGetSymbolAddress((void**)&tmp1, g_tmp1);
    cudaGetSymbolAddress((void**)&tmp2, g_tmp2);

    const int TB = 256;
    dim3 blkE((E + TB - 1) / TB);
    dim3 blkN((N + TB - 1) / TB);
    dim3 blkW((N * 32 + TB - 1) / TB);   // warp-per-node
    dim3 blkG((N + 127) / 128);          // 128-row GEMM tiles

    // Launch order keeps gemm1 in the profiled (4th) slot.
    zero_kernel<<<blkN, TB>>>(N);                        // 1
    count_kernel<<<blkE, TB>>>(adj, ew, E, N);           // 2
    scan_kernel<<<1, 1024>>>(N);                         // 3
    gemm_kernel<<<blkG, TB>>>(x, W1, tmp1, N);           // 4  <- profiled
    fill_kernel<<<blkE, TB>>>(adj, ew, E, N);            // 5

    // Layer 1 aggregate: tmp2 = relu(gather(tmp1) + b1)
    gather_kernel<false><<<blkW, TB>>>(tmp1, b1, nullptr, tmp2, N);  // 6

    // Layer 2: tmp1 = tmp2@W2 ; out = relu(gather(tmp1) + b2) + x
    gemm_kernel<<<blkG, TB>>>(tmp2, W2, tmp1, N);                    // 7
    gather_kernel<true><<<blkW, TB>>>(tmp1, b2, x, out, N);          // 8
}